// round 8
// baseline (speedup 1.0000x reference)
#include <cuda_runtime.h>
#include <cuda_bf16.h>
#include <cstdint>
#include <cstddef>

#define BB   4
#define CC   128
#define SS   32
#define OCC  128
#define EPSF 1e-8f

#define NSTAGE 54            // 27 taps * 2 ic-halves
#define A_BYTES 16384        // 128 oc x 128B (64 ic bf16)
#define B_BYTES 32768        // 256 n  x 128B
#define B_OFF   (4 * A_BYTES)
#define CTRL_OFF (B_OFF + 4 * B_BYTES)
#define SMEM_TOTAL (CTRL_OFF + 16)         // 192KB + ctrl
#define NTHR 512
#define NTILE 512
#define GRID 148

__device__ float g_demod[BB * OCC];
__device__ unsigned g_ctr;
__device__ __align__(256) __nv_bfloat16 g_whi[NSTAGE * 128 * 64];
__device__ __align__(256) __nv_bfloat16 g_wlo[NSTAGE * 128 * 64];
__device__ __align__(256) __nv_bfloat16 g_xhi[(size_t)BB * SS * SS * SS * CC];
__device__ __align__(256) __nv_bfloat16 g_xlo[(size_t)BB * SS * SS * SS * CC];

// ---------------- PTX helpers ----------------
__device__ __forceinline__ uint32_t smem_u32(const void* p) {
    uint32_t a;
    asm("{ .reg .u64 t; cvta.to.shared.u64 t, %1; cvt.u32.u64 %0, t; }" : "=r"(a) : "l"(p));
    return a;
}
__device__ __forceinline__ void cpasync16(uint32_t dst, const void* src, int sz) {
    asm volatile("cp.async.cg.shared.global [%0], [%1], 16, %2;"
                 :: "r"(dst), "l"(src), "r"(sz) : "memory");
}
#define CP_COMMIT() asm volatile("cp.async.commit_group;" ::: "memory")
#define CP_WAIT(n)  asm volatile("cp.async.wait_group %0;" :: "n"(n) : "memory")

__device__ __forceinline__ void ldsm4(uint32_t& r0, uint32_t& r1, uint32_t& r2,
                                      uint32_t& r3, uint32_t addr) {
    asm volatile("ldmatrix.sync.aligned.m8n8.x4.shared.b16 {%0,%1,%2,%3}, [%4];"
                 : "=r"(r0), "=r"(r1), "=r"(r2), "=r"(r3) : "r"(addr));
}
__device__ __forceinline__ void mma16816(float* c, const uint32_t* a, const uint32_t* b) {
    asm volatile(
        "mma.sync.aligned.m16n8k16.row.col.f32.bf16.bf16.f32 "
        "{%0,%1,%2,%3}, {%4,%5,%6,%7}, {%8,%9}, {%0,%1,%2,%3};"
        : "+f"(c[0]), "+f"(c[1]), "+f"(c[2]), "+f"(c[3])
        : "r"(a[0]), "r"(a[1]), "r"(a[2]), "r"(a[3]), "r"(b[0]), "r"(b[1]));
}
__device__ __forceinline__ uint32_t sw128(uint32_t off) { return off ^ ((off >> 3) & 0x70); }

// ---------------- prepass: demod (+ counter reset) ----------------
__global__ void demod_kernel(const float* __restrict__ y, const float* __restrict__ w) {
    int oc = blockIdx.x, ic = threadIdx.x;
    if (oc == 0 && ic == 0) g_ctr = GRID;
    const float* wp = w + (oc * CC + ic) * 27;
    float wsum = 0.f;
#pragma unroll
    for (int t = 0; t < 27; t++) { float v = wp[t]; wsum += v * v; }
    __shared__ float red[CC];
    for (int b = 0; b < BB; b++) {
        float yv = y[b * CC + ic];
        red[ic] = wsum * yv * yv;
        __syncthreads();
        for (int s = CC / 2; s > 0; s >>= 1) {
            if (ic < s) red[ic] += red[ic + s];
            __syncthreads();
        }
        if (ic == 0) g_demod[b * OCC + oc] = rsqrtf(red[0] + EPSF);
        __syncthreads();
    }
}

// ---------------- prepass: weight hi/lo split, [stage][oc][icl] ----------------
__global__ void wsplit_kernel(const float* __restrict__ w) {
    int oc = blockIdx.x, ic = threadIdx.x;
    int ichalf = ic >> 6, icl = ic & 63;
#pragma unroll 1
    for (int t = 0; t < 27; t++) {
        float v = w[(oc * CC + ic) * 27 + t];
        __nv_bfloat16 hi = __float2bfloat16(v);
        __nv_bfloat16 lo = __float2bfloat16(v - __bfloat162float(hi));
        int st = t * 2 + ichalf;
        g_whi[(st * 128 + oc) * 64 + icl] = hi;
        g_wlo[(st * 128 + oc) * 64 + icl] = lo;
    }
}

// ---------------- prepass: x transpose + y fold + split; [b,h,w,d][ic] ----------------
__global__ __launch_bounds__(256) void xsplit_kernel(const float* __restrict__ x,
                                                     const float* __restrict__ y) {
    __shared__ float ts[128][33];
    int w_ = blockIdx.x, h = blockIdx.y, b = blockIdx.z;
    int tid = threadIdx.x;
#pragma unroll
    for (int k = 0; k < 16; k++) {
        int e = tid + k * 256;
        int ic = e >> 5, d = e & 31;
        ts[ic][d] = x[((size_t)(b * CC + ic) * SS + h) * 1024 + w_ * SS + d] * y[b * CC + ic];
    }
    __syncthreads();
    size_t nb = (((size_t)(b * SS + h) * SS + w_) * SS) * CC;
#pragma unroll
    for (int k = 0; k < 16; k++) {
        int e = tid + k * 256;
        int d = e >> 7, ic = e & 127;
        float v = ts[ic][d];
        __nv_bfloat16 hi = __float2bfloat16(v);
        __nv_bfloat16 lo = __float2bfloat16(v - __bfloat162float(hi));
        g_xhi[nb + (size_t)d * CC + ic] = hi;
        g_xlo[nb + (size_t)d * CC + ic] = lo;
    }
}

// ---------------- stage loader (cp.async into buf) ----------------
__device__ __forceinline__ void load_stage(uint32_t sb, int tid, int s, int buf,
                                           int b, int h, int w0) {
    int tap = s >> 1, ichalf = s & 1;
    int kd = tap % 3, kw3 = tap / 3;
    int kw = kw3 % 3, kh = kw3 / 3;
    int gh = h + kh - 1;
    bool hok = (unsigned)gh < 32u;
    // A: 2 splits x 128 rows x 8 chunks of 16B = 2048 chunks
    {
        const char* wh = (const char*)(g_whi + (size_t)s * 128 * 64);
        const char* wl = (const char*)(g_wlo + (size_t)s * 128 * 64);
#pragma unroll
        for (int k = 0; k < 4; k++) {
            int i = tid + k * NTHR;
            int split = i >> 10, r = i & 1023;
            int row = r >> 3, c = r & 7;
            uint32_t off = (uint32_t)row * 128 + c * 16;
            uint32_t dst = sb + (buf * 2 + split) * A_BYTES + sw128(off);
            const char* src = (split ? wl : wh) + (size_t)row * 128 + c * 16;
            cpasync16(dst, src, 16);
        }
    }
    // B: 2 splits x 256 rows x 8 chunks = 4096 chunks
    {
#pragma unroll
        for (int k = 0; k < 8; k++) {
            int i = tid + k * NTHR;
            int split = i >> 11, r = i & 2047;
            int row = r >> 3, c = r & 7;
            int wl_ = row >> 5, d = row & 31;
            int gw = w0 + wl_ + kw - 1, gd = d + kd - 1;
            bool ok = hok && (unsigned)gw < 32u && (unsigned)gd < 32u;
            uint32_t off = (uint32_t)row * 128 + c * 16;
            uint32_t dst = sb + B_OFF + (buf * 2 + split) * B_BYTES + sw128(off);
            const __nv_bfloat16* xb = split ? g_xlo : g_xhi;
            size_t n = ok ? (((size_t)(b * SS + gh) * SS + gw) * SS + gd) : 0;
            const char* src = (const char*)xb + (n * CC + ichalf * 64) * 2 + c * 16;
            cpasync16(dst, src, ok ? 16 : 0);
        }
    }
    CP_COMMIT();
}

// ---------------- main conv: persistent mma.sync implicit GEMM ----------------
__global__ __launch_bounds__(NTHR, 1) void conv_kernel(float* __restrict__ out) {
    extern __shared__ char smem[];
    uint32_t sb = smem_u32(smem);
    unsigned* next_tile = (unsigned*)(smem + CTRL_OFF);
    int tid = threadIdx.x;
    int wid = tid >> 5, lid = tid & 31;

    // warp grid: 4m x 4n ; warp tile 32(M) x 64(N)
    int warp_m = (wid & 3) * 32;
    int warp_n = (wid >> 2) * 64;

    // per-lane swizzled ldmatrix base offsets (k-step applied via XOR)
    uint32_t sa[2], sbo[4];
#pragma unroll
    for (int mi = 0; mi < 2; mi++)
        sa[mi] = sw128((uint32_t)(warp_m + mi * 16 + (lid & 15)) * 128 + (lid >> 4) * 16);
#pragma unroll
    for (int nj2 = 0; nj2 < 4; nj2++)
        sbo[nj2] = sw128((uint32_t)(warp_n + nj2 * 16 + (lid & 7) + ((lid >> 4) & 1) * 8) * 128 +
                         ((lid >> 3) & 1) * 16);

    unsigned tile = blockIdx.x;
    while (tile < NTILE) {
        // tile -> (b, h, w-octile)
        int b  = tile >> 7;
        int h  = (tile >> 2) & 31;
        int w0 = (tile & 3) * 8;

        float acc[2][8][4];
#pragma unroll
        for (int mi = 0; mi < 2; mi++)
#pragma unroll
            for (int nj = 0; nj < 8; nj++)
#pragma unroll
                for (int q = 0; q < 4; q++) acc[mi][nj][q] = 0.f;

        load_stage(sb, tid, 0, 0, b, h, w0);

#pragma unroll 1
        for (int s = 1; s <= NSTAGE; s++) {
            if (s < NSTAGE) load_stage(sb, tid, s, s & 1, b, h, w0);
            int pb = (s - 1) & 1;
            if (s < NSTAGE) { CP_WAIT(1); } else { CP_WAIT(0); }
            __syncthreads();
            uint32_t Ah = sb + (pb * 2 + 0) * A_BYTES;   // wh
            uint32_t Al = sb + (pb * 2 + 1) * A_BYTES;   // wl
            uint32_t Bh = sb + B_OFF + (pb * 2 + 0) * B_BYTES;  // xh
            uint32_t Bl = sb + B_OFF + (pb * 2 + 1) * B_BYTES;  // xl
#pragma unroll
            for (int kk = 0; kk < 4; kk++) {
                uint32_t kx = (uint32_t)kk * 32;
                // load all shared operands once per kk
                uint32_t awh[2][4], awl[2][4];
#pragma unroll
                for (int mi = 0; mi < 2; mi++) {
                    ldsm4(awh[mi][0], awh[mi][1], awh[mi][2], awh[mi][3], Ah + (sa[mi] ^ kx));
                    ldsm4(awl[mi][0], awl[mi][1], awl[mi][2], awl[mi][3], Al + (sa[mi] ^ kx));
                }
                uint32_t bxh[8][2];
#pragma unroll
                for (int nj2 = 0; nj2 < 4; nj2++)
                    ldsm4(bxh[2 * nj2][0], bxh[2 * nj2][1], bxh[2 * nj2 + 1][0],
                          bxh[2 * nj2 + 1][1], Bh + (sbo[nj2] ^ kx));
                // term0: wh * xh
#pragma unroll
                for (int mi = 0; mi < 2; mi++)
#pragma unroll
                    for (int nj = 0; nj < 8; nj++)
                        mma16816(acc[mi][nj], awh[mi], bxh[nj]);
                // prefetch B_xl while term2 runs
                uint32_t bxl[8][2];
#pragma unroll
                for (int nj2 = 0; nj2 < 4; nj2++)
                    ldsm4(bxl[2 * nj2][0], bxl[2 * nj2][1], bxl[2 * nj2 + 1][0],
                          bxl[2 * nj2 + 1][1], Bl + (sbo[nj2] ^ kx));
                // term2: wl * xh
#pragma unroll
                for (int mi = 0; mi < 2; mi++)
#pragma unroll
                    for (int nj = 0; nj < 8; nj++)
                        mma16816(acc[mi][nj], awl[mi], bxh[nj]);
                // term1: wh * xl
#pragma unroll
                for (int mi = 0; mi < 2; mi++)
#pragma unroll
                    for (int nj = 0; nj < 8; nj++)
                        mma16816(acc[mi][nj], awh[mi], bxl[nj]);
            }
            __syncthreads();
        }

        // ---- epilogue: demod scale + float2 stores ----
#pragma unroll
        for (int mi = 0; mi < 2; mi++) {
#pragma unroll
            for (int rr = 0; rr < 2; rr++) {
                int oc = warp_m + mi * 16 + (lid >> 2) + rr * 8;
                float dm = g_demod[b * OCC + oc];
                float* obase = out + ((size_t)(b * OCC + oc) * SS + h) * 1024;
#pragma unroll
                for (int nj = 0; nj < 8; nj++) {
                    int n = warp_n + nj * 8 + 2 * (lid & 3);
                    int wl_ = n >> 5, d = n & 31;
                    float2 v;
                    v.x = acc[mi][nj][2 * rr + 0] * dm;
                    v.y = acc[mi][nj][2 * rr + 1] * dm;
                    *reinterpret_cast<float2*>(obase + (w0 + wl_) * 32 + d) = v;
                }
            }
        }

        // ---- next tile (dynamic) ----
        __syncthreads();
        if (tid == 0) *next_tile = atomicAdd(&g_ctr, 1u);
        __syncthreads();
        tile = *next_tile;
    }
}

// ---------------------------------------------------------------------------
extern "C" void kernel_launch(void* const* d_in, const int* in_sizes, int n_in,
                              void* d_out, int out_size) {
    const float* x = (const float*)d_in[0];
    const float* y = (const float*)d_in[1];
    const float* w = (const float*)d_in[2];
    float* out = (float*)d_out;

    cudaFuncSetAttribute(conv_kernel, cudaFuncAttributeMaxDynamicSharedMemorySize,
                         SMEM_TOTAL);

    demod_kernel<<<OCC, CC>>>(y, w);
    wsplit_kernel<<<OCC, CC>>>(w);
    xsplit_kernel<<<dim3(SS, SS, BB), 256>>>(x, y);
    conv_kernel<<<GRID, NTHR, SMEM_TOTAL>>>(out);
}

// round 9
// speedup vs baseline: 1.3876x; 1.3876x over previous
#include <cuda_runtime.h>
#include <cuda_fp16.h>
#include <cstdint>
#include <cstddef>

#define BB   4
#define CC   128
#define SS   32
#define OCC  128
#define EPSF 1e-8f

#define NSTAGE 54            // 27 taps * 2 ic-halves
#define A_BYTES 16384        // 128 oc x 128B (64 ic fp16)
#define B_BYTES 32768        // 256 n  x 128B
#define B_OFF   (2 * A_BYTES)
#define CTRL_OFF (B_OFF + 4 * B_BYTES)
#define SMEM_TOTAL (CTRL_OFF + 16)         // 160KB + ctrl
#define NTHR 512
#define NTILE 512
#define GRID 148

__device__ float g_demod[BB * OCC];
__device__ unsigned g_ctr;
__device__ __align__(256) __half g_w16[NSTAGE * 128 * 64];
__device__ __align__(256) __half g_xhi[(size_t)BB * SS * SS * SS * CC];
__device__ __align__(256) __half g_xlo[(size_t)BB * SS * SS * SS * CC];

// ---------------- PTX helpers ----------------
__device__ __forceinline__ uint32_t smem_u32(const void* p) {
    uint32_t a;
    asm("{ .reg .u64 t; cvta.to.shared.u64 t, %1; cvt.u32.u64 %0, t; }" : "=r"(a) : "l"(p));
    return a;
}
__device__ __forceinline__ void cpasync16(uint32_t dst, const void* src, int sz) {
    asm volatile("cp.async.cg.shared.global [%0], [%1], 16, %2;"
                 :: "r"(dst), "l"(src), "r"(sz) : "memory");
}
#define CP_COMMIT() asm volatile("cp.async.commit_group;" ::: "memory")
#define CP_WAIT(n)  asm volatile("cp.async.wait_group %0;" :: "n"(n) : "memory")

__device__ __forceinline__ void ldsm4(uint32_t& r0, uint32_t& r1, uint32_t& r2,
                                      uint32_t& r3, uint32_t addr) {
    asm volatile("ldmatrix.sync.aligned.m8n8.x4.shared.b16 {%0,%1,%2,%3}, [%4];"
                 : "=r"(r0), "=r"(r1), "=r"(r2), "=r"(r3) : "r"(addr));
}
__device__ __forceinline__ void mma16816(float* c, const uint32_t* a, const uint32_t* b) {
    asm volatile(
        "mma.sync.aligned.m16n8k16.row.col.f32.f16.f16.f32 "
        "{%0,%1,%2,%3}, {%4,%5,%6,%7}, {%8,%9}, {%0,%1,%2,%3};"
        : "+f"(c[0]), "+f"(c[1]), "+f"(c[2]), "+f"(c[3])
        : "r"(a[0]), "r"(a[1]), "r"(a[2]), "r"(a[3]), "r"(b[0]), "r"(b[1]));
}
__device__ __forceinline__ uint32_t sw128(uint32_t off) { return off ^ ((off >> 3) & 0x70); }

// ---------------- prepass: demod (+ counter reset) ----------------
__global__ void demod_kernel(const float* __restrict__ y, const float* __restrict__ w) {
    int oc = blockIdx.x, ic = threadIdx.x;
    if (oc == 0 && ic == 0) g_ctr = GRID;
    const float* wp = w + (oc * CC + ic) * 27;
    float wsum = 0.f;
#pragma unroll
    for (int t = 0; t < 27; t++) { float v = wp[t]; wsum += v * v; }
    __shared__ float red[CC];
    for (int b = 0; b < BB; b++) {
        float yv = y[b * CC + ic];
        red[ic] = wsum * yv * yv;
        __syncthreads();
        for (int s = CC / 2; s > 0; s >>= 1) {
            if (ic < s) red[ic] += red[ic + s];
            __syncthreads();
        }
        if (ic == 0) g_demod[b * OCC + oc] = rsqrtf(red[0] + EPSF);
        __syncthreads();
    }
}

// ---------------- prepass: weight fp16, layout [stage][oc][icl] ----------------
__global__ void wconv_kernel(const float* __restrict__ w) {
    int oc = blockIdx.x, ic = threadIdx.x;
    int ichalf = ic >> 6, icl = ic & 63;
#pragma unroll 1
    for (int t = 0; t < 27; t++) {
        float v = w[(oc * CC + ic) * 27 + t];
        int st = t * 2 + ichalf;
        g_w16[(st * 128 + oc) * 64 + icl] = __float2half(v);
    }
}

// ---------------- prepass: x transpose + y fold + fp16 hi/lo split ----------------
__global__ __launch_bounds__(256) void xsplit_kernel(const float* __restrict__ x,
                                                     const float* __restrict__ y) {
    __shared__ float ts[128][33];
    int w_ = blockIdx.x, h = blockIdx.y, b = blockIdx.z;
    int tid = threadIdx.x;
#pragma unroll
    for (int k = 0; k < 16; k++) {
        int e = tid + k * 256;
        int ic = e >> 5, d = e & 31;
        ts[ic][d] = x[((size_t)(b * CC + ic) * SS + h) * 1024 + w_ * SS + d] * y[b * CC + ic];
    }
    __syncthreads();
    size_t nb = (((size_t)(b * SS + h) * SS + w_) * SS) * CC;
#pragma unroll
    for (int k = 0; k < 16; k++) {
        int e = tid + k * 256;
        int d = e >> 7, ic = e & 127;
        float v = ts[ic][d];
        __half hi = __float2half(v);
        __half lo = __float2half(v - __half2float(hi));
        g_xhi[nb + (size_t)d * CC + ic] = hi;
        g_xlo[nb + (size_t)d * CC + ic] = lo;
    }
}

// ---------------- stage loader (cp.async into buf) ----------------
__device__ __forceinline__ void load_stage(uint32_t sb, int tid, int s, int buf,
                                           int b, int h, int w0) {
    int tap = s >> 1, ichalf = s & 1;
    int kd = tap % 3, kw3 = tap / 3;
    int kw = kw3 % 3, kh = kw3 / 3;
    int gh = h + kh - 1;
    bool hok = (unsigned)gh < 32u;
    // A: 128 rows x 8 chunks of 16B = 1024 chunks
    {
        const char* ws = (const char*)(g_w16 + (size_t)s * 128 * 64);
#pragma unroll
        for (int k = 0; k < 2; k++) {
            int i = tid + k * NTHR;
            int row = i >> 3, c = i & 7;
            uint32_t off = (uint32_t)row * 128 + c * 16;
            uint32_t dst = sb + buf * A_BYTES + sw128(off);
            cpasync16(dst, ws + (size_t)row * 128 + c * 16, 16);
        }
    }
    // B: 2 splits x 256 rows x 8 chunks = 4096 chunks
    {
#pragma unroll
        for (int k = 0; k < 8; k++) {
            int i = tid + k * NTHR;
            int split = i >> 11, r = i & 2047;
            int row = r >> 3, c = r & 7;
            int wl_ = row >> 5, d = row & 31;
            int gw = w0 + wl_ + kw - 1, gd = d + kd - 1;
            bool ok = hok && (unsigned)gw < 32u && (unsigned)gd < 32u;
            uint32_t off = (uint32_t)row * 128 + c * 16;
            uint32_t dst = sb + B_OFF + (buf * 2 + split) * B_BYTES + sw128(off);
            const __half* xb = split ? g_xlo : g_xhi;
            size_t n = ok ? (((size_t)(b * SS + gh) * SS + gw) * SS + gd) : 0;
            const char* src = (const char*)xb + (n * CC + ichalf * 64) * 2 + c * 16;
            cpasync16(dst, src, ok ? 16 : 0);
        }
    }
    CP_COMMIT();
}

// ---------------- main conv: persistent mma.sync implicit GEMM ----------------
__global__ __launch_bounds__(NTHR, 1) void conv_kernel(float* __restrict__ out) {
    extern __shared__ char smem[];
    uint32_t sb = smem_u32(smem);
    unsigned* next_tile = (unsigned*)(smem + CTRL_OFF);
    int tid = threadIdx.x;
    int wid = tid >> 5, lid = tid & 31;

    // warp grid: 4m x 4n ; warp tile 32(M) x 64(N)
    int warp_m = (wid & 3) * 32;
    int warp_n = (wid >> 2) * 64;

    // per-lane swizzled ldmatrix base offsets (k-step applied via XOR)
    uint32_t sa[2], sbo[4];
#pragma unroll
    for (int mi = 0; mi < 2; mi++)
        sa[mi] = sw128((uint32_t)(warp_m + mi * 16 + (lid & 15)) * 128 + (lid >> 4) * 16);
#pragma unroll
    for (int nj2 = 0; nj2 < 4; nj2++)
        sbo[nj2] = sw128((uint32_t)(warp_n + nj2 * 16 + (lid & 7) + ((lid >> 4) & 1) * 8) * 128 +
                         ((lid >> 3) & 1) * 16);

    unsigned tile = blockIdx.x;
    while (tile < NTILE) {
        int b  = tile >> 7;
        int h  = (tile >> 2) & 31;
        int w0 = (tile & 3) * 8;

        float acc[2][8][4];
#pragma unroll
        for (int mi = 0; mi < 2; mi++)
#pragma unroll
            for (int nj = 0; nj < 8; nj++)
#pragma unroll
                for (int q = 0; q < 4; q++) acc[mi][nj][q] = 0.f;

        load_stage(sb, tid, 0, 0, b, h, w0);

#pragma unroll 1
        for (int s = 1; s <= NSTAGE; s++) {
            if (s < NSTAGE) load_stage(sb, tid, s, s & 1, b, h, w0);
            int pb = (s - 1) & 1;
            if (s < NSTAGE) { CP_WAIT(1); } else { CP_WAIT(0); }
            __syncthreads();
            uint32_t Ab = sb + pb * A_BYTES;
            uint32_t Bh = sb + B_OFF + (pb * 2 + 0) * B_BYTES;
            uint32_t Bl = sb + B_OFF + (pb * 2 + 1) * B_BYTES;
#pragma unroll
            for (int kk = 0; kk < 4; kk++) {
                uint32_t kx = (uint32_t)kk * 32;
                uint32_t a[2][4];
#pragma unroll
                for (int mi = 0; mi < 2; mi++)
                    ldsm4(a[mi][0], a[mi][1], a[mi][2], a[mi][3], Ab + (sa[mi] ^ kx));
                // term0: w * xh
                {
                    uint32_t bf[8][2];
#pragma unroll
                    for (int nj2 = 0; nj2 < 4; nj2++)
                        ldsm4(bf[2 * nj2][0], bf[2 * nj2][1], bf[2 * nj2 + 1][0],
                              bf[2 * nj2 + 1][1], Bh + (sbo[nj2] ^ kx));
#pragma unroll
                    for (int mi = 0; mi < 2; mi++)
#pragma unroll
                        for (int nj = 0; nj < 8; nj++)
                            mma16816(acc[mi][nj], a[mi], bf[nj]);
                }
                // term1: w * xl
                {
                    uint32_t bf[8][2];
#pragma unroll
                    for (int nj2 = 0; nj2 < 4; nj2++)
                        ldsm4(bf[2 * nj2][0], bf[2 * nj2][1], bf[2 * nj2 + 1][0],
                              bf[2 * nj2 + 1][1], Bl + (sbo[nj2] ^ kx));
#pragma unroll
                    for (int mi = 0; mi < 2; mi++)
#pragma unroll
                        for (int nj = 0; nj < 8; nj++)
                            mma16816(acc[mi][nj], a[mi], bf[nj]);
                }
            }
            __syncthreads();
        }

        // ---- epilogue: demod scale + float2 stores ----
#pragma unroll
        for (int mi = 0; mi < 2; mi++) {
#pragma unroll
            for (int rr = 0; rr < 2; rr++) {
                int oc = warp_m + mi * 16 + (lid >> 2) + rr * 8;
                float dm = g_demod[b * OCC + oc];
                float* obase = out + ((size_t)(b * OCC + oc) * SS + h) * 1024;
#pragma unroll
                for (int nj = 0; nj < 8; nj++) {
                    int n = warp_n + nj * 8 + 2 * (lid & 3);
                    int wl_ = n >> 5, d = n & 31;
                    float2 v;
                    v.x = acc[mi][nj][2 * rr + 0] * dm;
                    v.y = acc[mi][nj][2 * rr + 1] * dm;
                    *reinterpret_cast<float2*>(obase + (w0 + wl_) * 32 + d) = v;
                }
            }
        }

        // ---- next tile (dynamic) ----
        __syncthreads();
        if (tid == 0) *next_tile = atomicAdd(&g_ctr, 1u);
        __syncthreads();
        tile = *next_tile;
    }
}

// ---------------------------------------------------------------------------
extern "C" void kernel_launch(void* const* d_in, const int* in_sizes, int n_in,
                              void* d_out, int out_size) {
    const float* x = (const float*)d_in[0];
    const float* y = (const float*)d_in[1];
    const float* w = (const float*)d_in[2];
    float* out = (float*)d_out;

    cudaFuncSetAttribute(conv_kernel, cudaFuncAttributeMaxDynamicSharedMemorySize,
                         SMEM_TOTAL);

    demod_kernel<<<OCC, CC>>>(y, w);
    wconv_kernel<<<OCC, CC>>>(w);
    xsplit_kernel<<<dim3(SS, SS, BB), 256>>>(x, y);
    conv_kernel<<<GRID, NTHR, SMEM_TOTAL>>>(out);
}

// round 10
// speedup vs baseline: 2.2465x; 1.6190x over previous
#include <cuda_runtime.h>
#include <cuda_fp16.h>
#include <cstdint>
#include <cstddef>

#define BB   4
#define CC   128
#define SS   32
#define OCC  128
#define EPSF 1e-8f

#define NSTAGE 54            // 27 taps * 2 ic-halves
#define A_BYTES 16384        // 128 oc x 128B (64 ic fp16)
#define B_BYTES 32768        // 256 n  x 128B
#define STG_BYTES (A_BYTES + B_BYTES)
#define NBUF 3
#define CTRL_OFF (NBUF * STG_BYTES)
#define SMEM_TOTAL (CTRL_OFF + 16)         // 144KB + ctrl
#define NTHR 512
#define NTILE 512
#define GRID 148

__device__ float g_demod[BB * OCC];
__device__ unsigned g_ctr;
__device__ __align__(256) __half g_w16[NSTAGE * 128 * 64];
__device__ __align__(256) __half g_x16[(size_t)BB * SS * SS * SS * CC];

// ---------------- PTX helpers ----------------
__device__ __forceinline__ uint32_t smem_u32(const void* p) {
    uint32_t a;
    asm("{ .reg .u64 t; cvta.to.shared.u64 t, %1; cvt.u32.u64 %0, t; }" : "=r"(a) : "l"(p));
    return a;
}
__device__ __forceinline__ void cpasync16(uint32_t dst, const void* src, int sz) {
    asm volatile("cp.async.cg.shared.global [%0], [%1], 16, %2;"
                 :: "r"(dst), "l"(src), "r"(sz) : "memory");
}
#define CP_COMMIT() asm volatile("cp.async.commit_group;" ::: "memory")
#define CP_WAIT(n)  asm volatile("cp.async.wait_group %0;" :: "n"(n) : "memory")

__device__ __forceinline__ void ldsm4(uint32_t& r0, uint32_t& r1, uint32_t& r2,
                                      uint32_t& r3, uint32_t addr) {
    asm volatile("ldmatrix.sync.aligned.m8n8.x4.shared.b16 {%0,%1,%2,%3}, [%4];"
                 : "=r"(r0), "=r"(r1), "=r"(r2), "=r"(r3) : "r"(addr));
}
__device__ __forceinline__ void mma16816(float* c, const uint32_t* a, const uint32_t* b) {
    asm volatile(
        "mma.sync.aligned.m16n8k16.row.col.f32.f16.f16.f32 "
        "{%0,%1,%2,%3}, {%4,%5,%6,%7}, {%8,%9}, {%0,%1,%2,%3};"
        : "+f"(c[0]), "+f"(c[1]), "+f"(c[2]), "+f"(c[3])
        : "r"(a[0]), "r"(a[1]), "r"(a[2]), "r"(a[3]), "r"(b[0]), "r"(b[1]));
}
__device__ __forceinline__ uint32_t sw128(uint32_t off) { return off ^ ((off >> 3) & 0x70); }

// ---------------- prepass: demod (+ counter reset) ----------------
__global__ void demod_kernel(const float* __restrict__ y, const float* __restrict__ w) {
    int oc = blockIdx.x, ic = threadIdx.x;
    if (oc == 0 && ic == 0) g_ctr = GRID;
    const float* wp = w + (oc * CC + ic) * 27;
    float wsum = 0.f;
#pragma unroll
    for (int t = 0; t < 27; t++) { float v = wp[t]; wsum += v * v; }
    __shared__ float red[CC];
    for (int b = 0; b < BB; b++) {
        float yv = y[b * CC + ic];
        red[ic] = wsum * yv * yv;
        __syncthreads();
        for (int s = CC / 2; s > 0; s >>= 1) {
            if (ic < s) red[ic] += red[ic + s];
            __syncthreads();
        }
        if (ic == 0) g_demod[b * OCC + oc] = rsqrtf(red[0] + EPSF);
        __syncthreads();
    }
}

// ---------------- prepass: weight fp16, layout [stage][oc][icl] ----------------
__global__ void wconv_kernel(const float* __restrict__ w) {
    int oc = blockIdx.x, ic = threadIdx.x;
    int ichalf = ic >> 6, icl = ic & 63;
#pragma unroll 1
    for (int t = 0; t < 27; t++) {
        float v = w[(oc * CC + ic) * 27 + t];
        int st = t * 2 + ichalf;
        g_w16[(st * 128 + oc) * 64 + icl] = __float2half(v);
    }
}

// ---------------- prepass: x transpose + y fold -> fp16; [b,h,w,d][ic] ----------------
__global__ __launch_bounds__(256) void xconv_kernel(const float* __restrict__ x,
                                                    const float* __restrict__ y) {
    __shared__ float ts[128][33];
    int w_ = blockIdx.x, h = blockIdx.y, b = blockIdx.z;
    int tid = threadIdx.x;
#pragma unroll
    for (int k = 0; k < 16; k++) {
        int e = tid + k * 256;
        int ic = e >> 5, d = e & 31;
        ts[ic][d] = x[((size_t)(b * CC + ic) * SS + h) * 1024 + w_ * SS + d] * y[b * CC + ic];
    }
    __syncthreads();
    size_t nb = (((size_t)(b * SS + h) * SS + w_) * SS) * CC;
#pragma unroll
    for (int k = 0; k < 16; k++) {
        int e = tid + k * 256;
        int d = e >> 7, ic = e & 127;
        g_x16[nb + (size_t)d * CC + ic] = __float2half(ts[ic][d]);
    }
}

// ---------------- stage loader (cp.async into buf) ----------------
__device__ __forceinline__ void load_stage(uint32_t sb, int tid, int s, int buf,
                                           int b, int h, int w0) {
    int tap = s >> 1, ichalf = s & 1;
    int kd = tap % 3, kw3 = tap / 3;
    int kw = kw3 % 3, kh = kw3 / 3;
    int gh = h + kh - 1;
    bool hok = (unsigned)gh < 32u;
    uint32_t base = sb + buf * STG_BYTES;
    // A: 128 rows x 8 chunks of 16B = 1024 chunks
    {
        const char* ws = (const char*)(g_w16 + (size_t)s * 128 * 64);
#pragma unroll
        for (int k = 0; k < 2; k++) {
            int i = tid + k * NTHR;
            int row = i >> 3, c = i & 7;
            uint32_t off = (uint32_t)row * 128 + c * 16;
            cpasync16(base + sw128(off), ws + (size_t)row * 128 + c * 16, 16);
        }
    }
    // B: 256 rows x 8 chunks = 2048 chunks
    {
#pragma unroll
        for (int k = 0; k < 4; k++) {
            int i = tid + k * NTHR;
            int row = i >> 3, c = i & 7;
            int wl_ = row >> 5, d = row & 31;
            int gw = w0 + wl_ + kw - 1, gd = d + kd - 1;
            bool ok = hok && (unsigned)gw < 32u && (unsigned)gd < 32u;
            uint32_t off = (uint32_t)row * 128 + c * 16;
            size_t n = ok ? (((size_t)(b * SS + gh) * SS + gw) * SS + gd) : 0;
            const char* src = (const char*)g_x16 + (n * CC + ichalf * 64) * 2 + c * 16;
            cpasync16(base + A_BYTES + sw128(off), src, ok ? 16 : 0);
        }
    }
    CP_COMMIT();
}

// ---------------- main conv: persistent mma.sync implicit GEMM ----------------
__global__ __launch_bounds__(NTHR, 1) void conv_kernel(float* __restrict__ out) {
    extern __shared__ char smem[];
    uint32_t sb = smem_u32(smem);
    unsigned* next_tile = (unsigned*)(smem + CTRL_OFF);
    int tid = threadIdx.x;
    int wid = tid >> 5, lid = tid & 31;

    // warp grid: 4m x 4n ; warp tile 32(M) x 64(N)
    int warp_m = (wid & 3) * 32;
    int warp_n = (wid >> 2) * 64;

    // per-lane swizzled ldmatrix base offsets (k-step applied via XOR)
    uint32_t sa[2], sbo[4];
#pragma unroll
    for (int mi = 0; mi < 2; mi++)
        sa[mi] = sw128((uint32_t)(warp_m + mi * 16 + (lid & 15)) * 128 + (lid >> 4) * 16);
#pragma unroll
    for (int nj2 = 0; nj2 < 4; nj2++)
        sbo[nj2] = sw128((uint32_t)(warp_n + nj2 * 16 + (lid & 7) + ((lid >> 4) & 1) * 8) * 128 +
                         ((lid >> 3) & 1) * 16);

    unsigned tile = blockIdx.x;
    while (tile < NTILE) {
        int b  = tile >> 7;
        int h  = (tile >> 2) & 31;
        int w0 = (tile & 3) * 8;

        float acc[2][8][4];
#pragma unroll
        for (int mi = 0; mi < 2; mi++)
#pragma unroll
            for (int nj = 0; nj < 8; nj++)
#pragma unroll
                for (int q = 0; q < 4; q++) acc[mi][nj][q] = 0.f;

        load_stage(sb, tid, 0, 0, b, h, w0);
        load_stage(sb, tid, 1, 1, b, h, w0);

        int buf = 0;
#pragma unroll 1
        for (int s = 0; s < NSTAGE; s++) {
            if (s + 2 < NSTAGE) {
                int nb = (s + 2) % NBUF;
                load_stage(sb, tid, s + 2, nb, b, h, w0);
                CP_WAIT(2);
            } else if (s + 1 < NSTAGE) {
                CP_WAIT(1);
            } else {
                CP_WAIT(0);
            }
            __syncthreads();
            uint32_t Ab = sb + buf * STG_BYTES;
            uint32_t Bb = Ab + A_BYTES;
#pragma unroll
            for (int kk = 0; kk < 4; kk++) {
                uint32_t kx = (uint32_t)kk * 32;
                uint32_t a[2][4];
#pragma unroll
                for (int mi = 0; mi < 2; mi++)
                    ldsm4(a[mi][0], a[mi][1], a[mi][2], a[mi][3], Ab + (sa[mi] ^ kx));
                uint32_t bf[8][2];
#pragma unroll
                for (int nj2 = 0; nj2 < 4; nj2++)
                    ldsm4(bf[2 * nj2][0], bf[2 * nj2][1], bf[2 * nj2 + 1][0],
                          bf[2 * nj2 + 1][1], Bb + (sbo[nj2] ^ kx));
#pragma unroll
                for (int mi = 0; mi < 2; mi++)
#pragma unroll
                    for (int nj = 0; nj < 8; nj++)
                        mma16816(acc[mi][nj], a[mi], bf[nj]);
            }
            __syncthreads();
            buf = (buf + 1 == NBUF) ? 0 : buf + 1;
        }

        // ---- epilogue: demod scale + float2 stores ----
#pragma unroll
        for (int mi = 0; mi < 2; mi++) {
#pragma unroll
            for (int rr = 0; rr < 2; rr++) {
                int oc = warp_m + mi * 16 + (lid >> 2) + rr * 8;
                float dm = g_demod[b * OCC + oc];
                float* obase = out + ((size_t)(b * OCC + oc) * SS + h) * 1024;
#pragma unroll
                for (int nj = 0; nj < 8; nj++) {
                    int n = warp_n + nj * 8 + 2 * (lid & 3);
                    int wl_ = n >> 5, d = n & 31;
                    float2 v;
                    v.x = acc[mi][nj][2 * rr + 0] * dm;
                    v.y = acc[mi][nj][2 * rr + 1] * dm;
                    *reinterpret_cast<float2*>(obase + (w0 + wl_) * 32 + d) = v;
                }
            }
        }

        // ---- next tile (dynamic) ----
        __syncthreads();
        if (tid == 0) *next_tile = atomicAdd(&g_ctr, 1u);
        __syncthreads();
        tile = *next_tile;
    }
}

// ---------------------------------------------------------------------------
extern "C" void kernel_launch(void* const* d_in, const int* in_sizes, int n_in,
                              void* d_out, int out_size) {
    const float* x = (const float*)d_in[0];
    const float* y = (const float*)d_in[1];
    const float* w = (const float*)d_in[2];
    float* out = (float*)d_out;

    cudaFuncSetAttribute(conv_kernel, cudaFuncAttributeMaxDynamicSharedMemorySize,
                         SMEM_TOTAL);

    demod_kernel<<<OCC, CC>>>(y, w);
    wconv_kernel<<<OCC, CC>>>(w);
    xconv_kernel<<<dim3(SS, SS, BB), 256>>>(x, y);
    conv_kernel<<<GRID, NTHR, SMEM_TOTAL>>>(out);
}

// round 11
// speedup vs baseline: 2.6874x; 1.1962x over previous
#include <cuda_runtime.h>
#include <cuda_fp16.h>
#include <cstdint>
#include <cstddef>

#define BB   4
#define CC   128
#define SS   32
#define OCC  128
#define EPSF 1e-8f

#define NTAP   27
#define BH_ROWS 1020                 // 3 planes x 10 w x 34 dd
#define BH_BYTES (BH_ROWS * 128)     // 130560
#define A_BYTES 16384                // 128 oc x 128B (64 ic fp16)
#define NBUF_A 4
#define A_OFF  BH_BYTES
#define CTRL_OFF (A_OFF + NBUF_A * A_BYTES)   // 196096
#define SMEM_TOTAL (CTRL_OFF + 16)
#define NTHR 512
#define NTILE 512
#define GRID 148

__device__ float g_demod[BB * OCC];
__device__ unsigned g_ctr;
__device__ __align__(256) __half g_w16[NTAP * 2 * 128 * 64];
__device__ __align__(256) __half g_x16[(size_t)BB * SS * SS * SS * CC];

// ---------------- PTX helpers ----------------
__device__ __forceinline__ uint32_t smem_u32(const void* p) {
    uint32_t a;
    asm("{ .reg .u64 t; cvta.to.shared.u64 t, %1; cvt.u32.u64 %0, t; }" : "=r"(a) : "l"(p));
    return a;
}
__device__ __forceinline__ void cpasync16(uint32_t dst, const void* src, int sz) {
    asm volatile("cp.async.cg.shared.global [%0], [%1], 16, %2;"
                 :: "r"(dst), "l"(src), "r"(sz) : "memory");
}
#define CP_COMMIT() asm volatile("cp.async.commit_group;" ::: "memory")
#define CP_WAIT(n)  asm volatile("cp.async.wait_group %0;" :: "n"(n) : "memory")

__device__ __forceinline__ void ldsm4(uint32_t& r0, uint32_t& r1, uint32_t& r2,
                                      uint32_t& r3, uint32_t addr) {
    asm volatile("ldmatrix.sync.aligned.m8n8.x4.shared.b16 {%0,%1,%2,%3}, [%4];"
                 : "=r"(r0), "=r"(r1), "=r"(r2), "=r"(r3) : "r"(addr));
}
__device__ __forceinline__ void mma16816(float* c, const uint32_t* a, const uint32_t* b) {
    asm volatile(
        "mma.sync.aligned.m16n8k16.row.col.f32.f16.f16.f32 "
        "{%0,%1,%2,%3}, {%4,%5,%6,%7}, {%8,%9}, {%0,%1,%2,%3};"
        : "+f"(c[0]), "+f"(c[1]), "+f"(c[2]), "+f"(c[3])
        : "r"(a[0]), "r"(a[1]), "r"(a[2]), "r"(a[3]), "r"(b[0]), "r"(b[1]));
}
__device__ __forceinline__ uint32_t sw128(uint32_t off) { return off ^ ((off >> 3) & 0x70); }
// swizzled addr of (row, colByte) in a 128B-row tile
__device__ __forceinline__ uint32_t rowaddr(uint32_t row, uint32_t colb) {
    return (row << 7) + (colb ^ ((row & 7) << 4));
}

// ---------------- prepass: demod (+ counter reset) ----------------
__global__ void demod_kernel(const float* __restrict__ y, const float* __restrict__ w) {
    int oc = blockIdx.x, ic = threadIdx.x;
    if (oc == 0 && ic == 0) g_ctr = GRID;
    const float* wp = w + (oc * CC + ic) * 27;
    float wsum = 0.f;
#pragma unroll
    for (int t = 0; t < 27; t++) { float v = wp[t]; wsum += v * v; }
    __shared__ float red[CC];
    for (int b = 0; b < BB; b++) {
        float yv = y[b * CC + ic];
        red[ic] = wsum * yv * yv;
        __syncthreads();
        for (int s = CC / 2; s > 0; s >>= 1) {
            if (ic < s) red[ic] += red[ic + s];
            __syncthreads();
        }
        if (ic == 0) g_demod[b * OCC + oc] = rsqrtf(red[0] + EPSF);
        __syncthreads();
    }
}

// ---------------- prepass: weight fp16, layout [tap*2+ichalf][oc][icl] ----------------
__global__ void wconv_kernel(const float* __restrict__ w) {
    int oc = blockIdx.x, ic = threadIdx.x;
    int ichalf = ic >> 6, icl = ic & 63;
#pragma unroll 1
    for (int t = 0; t < 27; t++) {
        float v = w[(oc * CC + ic) * 27 + t];
        int st = t * 2 + ichalf;
        g_w16[(st * 128 + oc) * 64 + icl] = __float2half(v);
    }
}

// ---------------- prepass: x transpose + y fold -> fp16; [b,h,w,d][ic] ----------------
__global__ __launch_bounds__(256) void xconv_kernel(const float* __restrict__ x,
                                                    const float* __restrict__ y) {
    __shared__ float ts[128][33];
    int w_ = blockIdx.x, h = blockIdx.y, b = blockIdx.z;
    int tid = threadIdx.x;
#pragma unroll
    for (int k = 0; k < 16; k++) {
        int e = tid + k * 256;
        int ic = e >> 5, d = e & 31;
        ts[ic][d] = x[((size_t)(b * CC + ic) * SS + h) * 1024 + w_ * SS + d] * y[b * CC + ic];
    }
    __syncthreads();
    size_t nb = (((size_t)(b * SS + h) * SS + w_) * SS) * CC;
#pragma unroll
    for (int k = 0; k < 16; k++) {
        int e = tid + k * 256;
        int d = e >> 7, ic = e & 127;
        g_x16[nb + (size_t)d * CC + ic] = __float2half(ts[ic][d]);
    }
}

// ---------------- B halo loader: 1020 rows, zero-filled halo ----------------
__device__ __forceinline__ void load_bhalo(uint32_t sb, int tid, int pass,
                                           int b, int h, int w0) {
#pragma unroll 1
    for (int k = 0; k < 16; k++) {
        int i = tid + k * NTHR;
        if (i < BH_ROWS * 8) {
            int r = i >> 3, c = i & 7;
            int plane = r / 340;
            int rem   = r - plane * 340;
            int lw    = rem / 34;
            int dd    = rem - lw * 34;
            int gh = h + plane - 1, gw = w0 + lw - 1, gd = dd - 1;
            bool ok = (unsigned)gh < 32u && (unsigned)gw < 32u && (unsigned)gd < 32u;
            size_t n = ok ? (((size_t)(b * SS + gh) * SS + gw) * SS + gd) : 0;
            const char* src = (const char*)g_x16 + (n * CC + pass * 64) * 2 + c * 16;
            cpasync16(sb + rowaddr((uint32_t)r, c * 16), src, ok ? 16 : 0);
        }
    }
    CP_COMMIT();
}

// ---------------- A loader: one (tap, ichalf) slice, 16KB ----------------
__device__ __forceinline__ void load_a(uint32_t sb, int tid, int tap, int pass, int buf) {
    const char* ws = (const char*)(g_w16 + (size_t)(tap * 2 + pass) * 128 * 64);
    uint32_t base = sb + A_OFF + buf * A_BYTES;
#pragma unroll
    for (int k = 0; k < 2; k++) {
        int i = tid + k * NTHR;
        int row = i >> 3, c = i & 7;
        cpasync16(base + rowaddr((uint32_t)row, c * 16), ws + (size_t)row * 128 + c * 16, 16);
    }
    CP_COMMIT();
}

// ---------------- main conv: persistent implicit GEMM, halo-B reuse ----------------
__global__ __launch_bounds__(NTHR, 1) void conv_kernel(float* __restrict__ out) {
    extern __shared__ char smem[];
    uint32_t sb = smem_u32(smem);
    unsigned* next_tile = (unsigned*)(smem + CTRL_OFF);
    int tid = threadIdx.x;
    int wid = tid >> 5, lid = tid & 31;

    // warp grid: 4m x 4n ; warp tile 32(M) x 64(N)
    int warp_m = (wid & 3) * 32;
    int warp_n = (wid >> 2) * 64;

    // A: per-lane swizzled base offsets (within a 16KB A buffer)
    uint32_t sa[2];
#pragma unroll
    for (int mi = 0; mi < 2; mi++)
        sa[mi] = rowaddr((uint32_t)(warp_m + mi * 16 + (lid & 15)), (lid >> 4) * 16);

    // B: per-lane halo row base (n -> wl*34 + d) and col byte
    uint32_t brow[4];
    uint32_t bcol = ((lid >> 3) & 1) * 16;
#pragma unroll
    for (int nj2 = 0; nj2 < 4; nj2++) {
        int n = warp_n + nj2 * 16 + (lid & 7) + ((lid >> 4) & 1) * 8;
        brow[nj2] = (uint32_t)((n >> 5) * 34 + (n & 31));
    }

    unsigned tile = blockIdx.x;
    while (tile < NTILE) {
        int b  = tile >> 7;
        int h  = (tile >> 2) & 31;
        int w0 = (tile & 3) * 8;

        float acc[2][8][4];
#pragma unroll
        for (int mi = 0; mi < 2; mi++)
#pragma unroll
            for (int nj = 0; nj < 8; nj++)
#pragma unroll
                for (int q = 0; q < 4; q++) acc[mi][nj][q] = 0.f;

#pragma unroll 1
        for (int pass = 0; pass < 2; pass++) {
            __syncthreads();                       // prior pass readers done
            load_bhalo(sb, tid, pass, b, h, w0);   // group
            load_a(sb, tid, 0, pass, 0);           // group
            load_a(sb, tid, 1, pass, 1);           // group

#pragma unroll 1
            for (int t = 0; t < NTAP; t++) {
                if (t + 2 < NTAP) {
                    load_a(sb, tid, t + 2, pass, (t + 2) & 3);
                    CP_WAIT(2);
                } else if (t + 1 < NTAP) {
                    CP_WAIT(1);
                } else {
                    CP_WAIT(0);
                }
                __syncthreads();

                // tap offsets
                int kh = t / 9, r9 = t - kh * 9;
                int kw = r9 / 3, kd = r9 - kw * 3;
                uint32_t tapoff = (uint32_t)(kh * 340 + kw * 34 + kd);

                uint32_t Ab = sb + A_OFF + (t & 3) * A_BYTES;
                uint32_t sbb[4];
#pragma unroll
                for (int nj2 = 0; nj2 < 4; nj2++)
                    sbb[nj2] = sb + rowaddr(brow[nj2] + tapoff, bcol);

#pragma unroll
                for (int kk = 0; kk < 4; kk++) {
                    uint32_t kx = (uint32_t)kk * 32;
                    uint32_t a[2][4];
#pragma unroll
                    for (int mi = 0; mi < 2; mi++)
                        ldsm4(a[mi][0], a[mi][1], a[mi][2], a[mi][3], Ab + (sa[mi] ^ kx));
                    uint32_t bf[8][2];
#pragma unroll
                    for (int nj2 = 0; nj2 < 4; nj2++)
                        ldsm4(bf[2 * nj2][0], bf[2 * nj2][1], bf[2 * nj2 + 1][0],
                              bf[2 * nj2 + 1][1], sbb[nj2] ^ kx);
#pragma unroll
                    for (int mi = 0; mi < 2; mi++)
#pragma unroll
                        for (int nj = 0; nj < 8; nj++)
                            mma16816(acc[mi][nj], a[mi], bf[nj]);
                }
            }
        }

        // ---- epilogue: demod scale + float2 stores ----
#pragma unroll
        for (int mi = 0; mi < 2; mi++) {
#pragma unroll
            for (int rr = 0; rr < 2; rr++) {
                int oc = warp_m + mi * 16 + (lid >> 2) + rr * 8;
                float dm = g_demod[b * OCC + oc];
                float* obase = out + ((size_t)(b * OCC + oc) * SS + h) * 1024;
#pragma unroll
                for (int nj = 0; nj < 8; nj++) {
                    int n = warp_n + nj * 8 + 2 * (lid & 3);
                    int wl_ = n >> 5, d = n & 31;
                    float2 v;
                    v.x = acc[mi][nj][2 * rr + 0] * dm;
                    v.y = acc[mi][nj][2 * rr + 1] * dm;
                    *reinterpret_cast<float2*>(obase + (w0 + wl_) * 32 + d) = v;
                }
            }
        }

        // ---- next tile (dynamic) ----
        __syncthreads();
        if (tid == 0) *next_tile = atomicAdd(&g_ctr, 1u);
        __syncthreads();
        tile = *next_tile;
    }
}

// ---------------------------------------------------------------------------
extern "C" void kernel_launch(void* const* d_in, const int* in_sizes, int n_in,
                              void* d_out, int out_size) {
    const float* x = (const float*)d_in[0];
    const float* y = (const float*)d_in[1];
    const float* w = (const float*)d_in[2];
    float* out = (float*)d_out;

    cudaFuncSetAttribute(conv_kernel, cudaFuncAttributeMaxDynamicSharedMemorySize,
                         SMEM_TOTAL);

    demod_kernel<<<OCC, CC>>>(y, w);
    wconv_kernel<<<OCC, CC>>>(w);
    xconv_kernel<<<dim3(SS, SS, BB), 256>>>(x, y);
    conv_kernel<<<GRID, NTHR, SMEM_TOTAL>>>(out);
}

// round 12
// speedup vs baseline: 2.7816x; 1.0350x over previous
#include <cuda_runtime.h>
#include <cuda_fp16.h>
#include <cstdint>
#include <cstddef>

#define BB   4
#define CC   128
#define SS   32
#define OCC  128
#define EPSF 1e-8f

#define NTAP   27
#define BH_ROWS 1020                 // 3 planes x 10 w x 34 dd
#define BH_BYTES (BH_ROWS * 128)     // 130560
#define A_BYTES 16384                // 128 oc x 128B (64 ic fp16)
#define NBUF_A 6
#define A_OFF  BH_BYTES
#define CTRL_OFF (A_OFF + NBUF_A * A_BYTES)   // 228864
#define SMEM_TOTAL (CTRL_OFF + 16)
#define NTHR 512
#define NTILE 512
#define GRID 148

__device__ float g_demod[BB * OCC];
__device__ unsigned g_ctr;
__device__ __align__(256) __half g_w16[NTAP * 2 * 128 * 64];
__device__ __align__(256) __half g_x16[(size_t)BB * SS * SS * SS * CC];

// ---------------- PTX helpers ----------------
__device__ __forceinline__ uint32_t smem_u32(const void* p) {
    uint32_t a;
    asm("{ .reg .u64 t; cvta.to.shared.u64 t, %1; cvt.u32.u64 %0, t; }" : "=r"(a) : "l"(p));
    return a;
}
__device__ __forceinline__ void cpasync16(uint32_t dst, const void* src, int sz) {
    asm volatile("cp.async.cg.shared.global [%0], [%1], 16, %2;"
                 :: "r"(dst), "l"(src), "r"(sz) : "memory");
}
#define CP_COMMIT() asm volatile("cp.async.commit_group;" ::: "memory")
#define CP_WAIT(n)  asm volatile("cp.async.wait_group %0;" :: "n"(n) : "memory")

__device__ __forceinline__ void ldsm4(uint32_t& r0, uint32_t& r1, uint32_t& r2,
                                      uint32_t& r3, uint32_t addr) {
    asm volatile("ldmatrix.sync.aligned.m8n8.x4.shared.b16 {%0,%1,%2,%3}, [%4];"
                 : "=r"(r0), "=r"(r1), "=r"(r2), "=r"(r3) : "r"(addr));
}
__device__ __forceinline__ void mma16816(float* c, const uint32_t* a, const uint32_t* b) {
    asm volatile(
        "mma.sync.aligned.m16n8k16.row.col.f32.f16.f16.f32 "
        "{%0,%1,%2,%3}, {%4,%5,%6,%7}, {%8,%9}, {%0,%1,%2,%3};"
        : "+f"(c[0]), "+f"(c[1]), "+f"(c[2]), "+f"(c[3])
        : "r"(a[0]), "r"(a[1]), "r"(a[2]), "r"(a[3]), "r"(b[0]), "r"(b[1]));
}
// swizzled addr of (row, colByte) in a 128B-row tile
__device__ __forceinline__ uint32_t rowaddr(uint32_t row, uint32_t colb) {
    return (row << 7) + (colb ^ ((row & 7) << 4));
}

// ---------------- prepass: demod (+ counter reset) ----------------
__global__ void demod_kernel(const float* __restrict__ y, const float* __restrict__ w) {
    int oc = blockIdx.x, ic = threadIdx.x;
    if (oc == 0 && ic == 0) g_ctr = GRID;
    const float* wp = w + (oc * CC + ic) * 27;
    float wsum = 0.f;
#pragma unroll
    for (int t = 0; t < 27; t++) { float v = wp[t]; wsum += v * v; }
    __shared__ float red[CC];
    for (int b = 0; b < BB; b++) {
        float yv = y[b * CC + ic];
        red[ic] = wsum * yv * yv;
        __syncthreads();
        for (int s = CC / 2; s > 0; s >>= 1) {
            if (ic < s) red[ic] += red[ic + s];
            __syncthreads();
        }
        if (ic == 0) g_demod[b * OCC + oc] = rsqrtf(red[0] + EPSF);
        __syncthreads();
    }
}

// ---------------- prepass: weight fp16, layout [tap*2+ichalf][oc][icl] ----------------
__global__ void wconv_kernel(const float* __restrict__ w) {
    int oc = blockIdx.x, ic = threadIdx.x;
    int ichalf = ic >> 6, icl = ic & 63;
#pragma unroll 1
    for (int t = 0; t < 27; t++) {
        float v = w[(oc * CC + ic) * 27 + t];
        int st = t * 2 + ichalf;
        g_w16[(st * 128 + oc) * 64 + icl] = __float2half(v);
    }
}

// ---------------- prepass: x transpose + y fold -> fp16; [b,h,w,d][ic] ----------------
__global__ __launch_bounds__(256) void xconv_kernel(const float* __restrict__ x,
                                                    const float* __restrict__ y) {
    __shared__ float ts[128][33];
    int w_ = blockIdx.x, h = blockIdx.y, b = blockIdx.z;
    int tid = threadIdx.x;
#pragma unroll
    for (int k = 0; k < 16; k++) {
        int e = tid + k * 256;
        int ic = e >> 5, d = e & 31;
        ts[ic][d] = x[((size_t)(b * CC + ic) * SS + h) * 1024 + w_ * SS + d] * y[b * CC + ic];
    }
    __syncthreads();
    size_t nb = (((size_t)(b * SS + h) * SS + w_) * SS) * CC;
#pragma unroll
    for (int k = 0; k < 16; k++) {
        int e = tid + k * 256;
        int d = e >> 7, ic = e & 127;
        g_x16[nb + (size_t)d * CC + ic] = __float2half(ts[ic][d]);
    }
}

// ---------------- B halo loader: 1020 rows, zero-filled halo ----------------
__device__ __forceinline__ void load_bhalo(uint32_t sb, int tid, int pass,
                                           int b, int h, int w0) {
#pragma unroll 1
    for (int k = 0; k < 16; k++) {
        int i = tid + k * NTHR;
        if (i < BH_ROWS * 8) {
            int r = i >> 3, c = i & 7;
            int plane = r / 340;
            int rem   = r - plane * 340;
            int lw    = rem / 34;
            int dd    = rem - lw * 34;
            int gh = h + plane - 1, gw = w0 + lw - 1, gd = dd - 1;
            bool ok = (unsigned)gh < 32u && (unsigned)gw < 32u && (unsigned)gd < 32u;
            size_t n = ok ? (((size_t)(b * SS + gh) * SS + gw) * SS + gd) : 0;
            const char* src = (const char*)g_x16 + (n * CC + pass * 64) * 2 + c * 16;
            cpasync16(sb + rowaddr((uint32_t)r, c * 16), src, ok ? 16 : 0);
        }
    }
    CP_COMMIT();
}

// ---------------- A group loader: taps 3g..3g+2 into buffer set (g&1)*3 ----------------
__device__ __forceinline__ void load_agroup(uint32_t sb, int tid, int g, int pass) {
    int bufbase = (g & 1) * 3;
#pragma unroll
    for (int i = 0; i < 3; i++) {
        int tap = g * 3 + i;
        const char* ws = (const char*)(g_w16 + (size_t)(tap * 2 + pass) * 128 * 64);
        uint32_t base = sb + A_OFF + (bufbase + i) * A_BYTES;
#pragma unroll
        for (int k = 0; k < 2; k++) {
            int idx = tid + k * NTHR;
            int row = idx >> 3, c = idx & 7;
            cpasync16(base + rowaddr((uint32_t)row, c * 16),
                      ws + (size_t)row * 128 + c * 16, 16);
        }
    }
    CP_COMMIT();
}

// ---------------- main conv: persistent implicit GEMM, halo-B reuse ----------------
__global__ __launch_bounds__(NTHR, 1) void conv_kernel(float* __restrict__ out) {
    extern __shared__ char smem[];
    uint32_t sb = smem_u32(smem);
    unsigned* next_tile = (unsigned*)(smem + CTRL_OFF);
    int tid = threadIdx.x;
    int wid = tid >> 5, lid = tid & 31;

    // warp grid: 4m x 4n ; warp tile 32(M) x 64(N)
    int warp_m = (wid & 3) * 32;
    int warp_n = (wid >> 2) * 64;

    // A: per-lane swizzled base offsets (within a 16KB A buffer)
    uint32_t sa[2];
#pragma unroll
    for (int mi = 0; mi < 2; mi++)
        sa[mi] = rowaddr((uint32_t)(warp_m + mi * 16 + (lid & 15)), (lid >> 4) * 16);

    // B: per-lane halo row base (n -> wl*34 + d) and col byte
    uint32_t brow[4];
    uint32_t bcol = ((lid >> 3) & 1) * 16;
#pragma unroll
    for (int nj2 = 0; nj2 < 4; nj2++) {
        int n = warp_n + nj2 * 16 + (lid & 7) + ((lid >> 4) & 1) * 8;
        brow[nj2] = (uint32_t)((n >> 5) * 34 + (n & 31));
    }

    unsigned tile = blockIdx.x;
    while (tile < NTILE) {
        int b  = tile >> 7;
        int h  = (tile >> 2) & 31;
        int w0 = (tile & 3) * 8;

        float acc[2][8][4];
#pragma unroll
        for (int mi = 0; mi < 2; mi++)
#pragma unroll
            for (int nj = 0; nj < 8; nj++)
#pragma unroll
                for (int q = 0; q < 4; q++) acc[mi][nj][q] = 0.f;

#pragma unroll 1
        for (int pass = 0; pass < 2; pass++) {
            __syncthreads();                       // prior readers done (bhalo + A bufs)
            load_bhalo(sb, tid, pass, b, h, w0);   // commit
            load_agroup(sb, tid, 0, pass);         // commit

#pragma unroll 1
            for (int g = 0; g < 9; g++) {
                CP_WAIT(0);            // group g (and bhalo at g=0) resident
                __syncthreads();       // all warps done with set (g-1)&1 == (g+1)&1
                if (g < 8) load_agroup(sb, tid, g + 1, pass);  // hidden under compute

#pragma unroll
                for (int i = 0; i < 3; i++) {
                    int t = g * 3 + i;
                    int kh = t / 9, r9 = t - kh * 9;
                    int kw = r9 / 3, kd = r9 - kw * 3;
                    uint32_t tapoff = (uint32_t)(kh * 340 + kw * 34 + kd);

                    uint32_t Ab = sb + A_OFF + ((g & 1) * 3 + i) * A_BYTES;
                    uint32_t sbb[4];
#pragma unroll
                    for (int nj2 = 0; nj2 < 4; nj2++)
                        sbb[nj2] = sb + rowaddr(brow[nj2] + tapoff, bcol);

#pragma unroll
                    for (int kk = 0; kk < 4; kk++) {
                        uint32_t kx = (uint32_t)kk * 32;
                        uint32_t a[2][4];
#pragma unroll
                        for (int mi = 0; mi < 2; mi++)
                            ldsm4(a[mi][0], a[mi][1], a[mi][2], a[mi][3], Ab + (sa[mi] ^ kx));
                        uint32_t bf[8][2];
#pragma unroll
                        for (int nj2 = 0; nj2 < 4; nj2++)
                            ldsm4(bf[2 * nj2][0], bf[2 * nj2][1], bf[2 * nj2 + 1][0],
                                  bf[2 * nj2 + 1][1], sbb[nj2] ^ kx);
#pragma unroll
                        for (int mi = 0; mi < 2; mi++)
#pragma unroll
                            for (int nj = 0; nj < 8; nj++)
                                mma16816(acc[mi][nj], a[mi], bf[nj]);
                    }
                }
            }
        }

        // ---- epilogue: demod scale + float2 stores ----
#pragma unroll
        for (int mi = 0; mi < 2; mi++) {
#pragma unroll
            for (int rr = 0; rr < 2; rr++) {
                int oc = warp_m + mi * 16 + (lid >> 2) + rr * 8;
                float dm = g_demod[b * OCC + oc];
                float* obase = out + ((size_t)(b * OCC + oc) * SS + h) * 1024;
#pragma unroll
                for (int nj = 0; nj < 8; nj++) {
                    int n = warp_n + nj * 8 + 2 * (lid & 3);
                    int wl_ = n >> 5, d = n & 31;
                    float2 v;
                    v.x = acc[mi][nj][2 * rr + 0] * dm;
                    v.y = acc[mi][nj][2 * rr + 1] * dm;
                    *reinterpret_cast<float2*>(obase + (w0 + wl_) * 32 + d) = v;
                }
            }
        }

        // ---- next tile (dynamic) ----
        __syncthreads();
        if (tid == 0) *next_tile = atomicAdd(&g_ctr, 1u);
        __syncthreads();
        tile = *next_tile;
    }
}

// ---------------------------------------------------------------------------
extern "C" void kernel_launch(void* const* d_in, const int* in_sizes, int n_in,
                              void* d_out, int out_size) {
    const float* x = (const float*)d_in[0];
    const float* y = (const float*)d_in[1];
    const float* w = (const float*)d_in[2];
    float* out = (float*)d_out;

    cudaFuncSetAttribute(conv_kernel, cudaFuncAttributeMaxDynamicSharedMemorySize,
                         SMEM_TOTAL);

    demod_kernel<<<OCC, CC>>>(y, w);
    wconv_kernel<<<OCC, CC>>>(w);
    xconv_kernel<<<dim3(SS, SS, BB), 256>>>(x, y);
    conv_kernel<<<GRID, NTHR, SMEM_TOTAL>>>(out);
}